// round 8
// baseline (speedup 1.0000x reference)
#include <cuda_runtime.h>

// CLUBLoss, single-pass single-launch with double global accumulation.
//   x        : (B=16, D=512, H=32, W=32) f32
//   p_mu     : (N=16384, D=512) f32,  n = b*H*W + h*W + w
//   p_logvar : (N=16384, D=512) f32
//
// sum_i loss_i * (-2) = A + sum_d( -m2_d*S_d + 2*m1_d*T_d )
//   A    = sum_{i,d} (x^2 - 2*mu*x) * exp(-lv)
//   S_d  = sum_i exp(-lv),  T_d = sum_i mu*exp(-lv)
//   m1_d = SX_d/N, m2_d = SX2_d/N
// out = -0.5/N * (A + corr).  All global sums accumulated in DOUBLE
// (the fp32 version of this cancellation failed at rel 2.3e-3 in R4).

#define DI      512
#define BB      16
#define HH      32
#define WW      32
#define NN      (BB * HH * WW)
#define SPATIAL (HH * WW)
#define DH      128
#define NBLK    2048      // 512 (b,h) tiles * 4 d-quarters
#define PITCH   132       // 33*4 -> 16B-aligned rows, conflict-free LDS.128

__device__ double g_S[DI];
__device__ double g_T[DI];
__device__ double g_SX[DI];
__device__ double g_SX2[DI];
__device__ double g_A;
__device__ unsigned int g_count;

__global__ void __launch_bounds__(256) club_kernel(const float* __restrict__ x,
                                                   const float* __restrict__ mu,
                                                   const float* __restrict__ lv,
                                                   float* __restrict__ out) {
    const int bh    = blockIdx.x >> 2;    // b*32 + h
    const int dpart = blockIdx.x & 3;
    const int b     = bh >> 5;
    const int h     = bh & 31;
    const int doff  = dpart * DH;
    const int n0    = bh * WW;

    __shared__ float xs[WW * PITCH];      // 16.9 KB x slab [w*PITCH + d_local]
    float* redc = xs;                     // aliased after xs is dead: [8][32][8]
    float* redA = xs + 2048;              // 256 floats
    __shared__ int sLast;

    const int t  = threadIdx.x;
    const int dq = t & 31;                // d-quad (4 cols)
    const int wg = t >> 5;                // token group (4 tokens)
    const int d0 = dq * 4;

    // ---- stage x slab: coalesced float4, 4 per thread ----
    const float4* xbase = (const float4*)(x + (size_t)b * (DI * SPATIAL)
                                            + (size_t)doff * SPATIAL
                                            + (size_t)h * WW);
    #pragma unroll
    for (int it = 0; it < 4; ++it) {
        const int i  = t + it * 256;
        const int dr = i >> 3;
        const int q  = i & 7;
        const float4 v = xbase[(size_t)dr * (SPATIAL / 4) + q];
        float* row = &xs[(q * 4) * PITCH + dr];
        row[0]         = v.x;
        row[PITCH]     = v.y;
        row[2 * PITCH] = v.z;
        row[3 * PITCH] = v.w;
    }
    __syncthreads();

    // ---- per-column SX / SX2 straight from the slab (t<128, d_local=t) ----
    float csx = 0.f, csx2 = 0.f;
    if (t < DH) {
        #pragma unroll 8
        for (int w = 0; w < WW; ++w) {
            const float v = xs[w * PITCH + t];
            csx  += v;
            csx2 += v * v;
        }
    }

    // ---- main loop: A, S, T over 4 tokens x 4 cols ----
    float accA = 0.f;
    float sS[4] = {0, 0, 0, 0};
    float sT[4] = {0, 0, 0, 0};
    const size_t rbase = ((size_t)(n0 + wg * 4) * DI + doff) / 4 + dq;

    #pragma unroll
    for (int gg = 0; gg < 2; ++gg) {
        float4 ma = ((const float4*)mu)[rbase + (size_t)(2 * gg + 0) * (DI / 4)];
        float4 la = ((const float4*)lv)[rbase + (size_t)(2 * gg + 0) * (DI / 4)];
        float4 mb = ((const float4*)mu)[rbase + (size_t)(2 * gg + 1) * (DI / 4)];
        float4 lb = ((const float4*)lv)[rbase + (size_t)(2 * gg + 1) * (DI / 4)];
        #pragma unroll
        for (int k = 0; k < 2; ++k) {
            const int w = wg * 4 + 2 * gg + k;
            const float4 m = k ? mb : ma;
            const float4 l = k ? lb : la;
            const float4 v = *(const float4*)&xs[w * PITCH + d0];  // 16B aligned
            const float i0 = __expf(-l.x), i1 = __expf(-l.y);
            const float i2 = __expf(-l.z), i3 = __expf(-l.w);
            accA += (v.x * v.x - 2.f * m.x * v.x) * i0;
            accA += (v.y * v.y - 2.f * m.y * v.y) * i1;
            accA += (v.z * v.z - 2.f * m.z * v.z) * i2;
            accA += (v.w * v.w - 2.f * m.w * v.w) * i3;
            sS[0] += i0; sS[1] += i1; sS[2] += i2; sS[3] += i3;
            sT[0] += m.x * i0; sT[1] += m.y * i1;
            sT[2] += m.z * i2; sT[3] += m.w * i3;
        }
    }
    __syncthreads();      // xs dead; safe to alias

    // ---- stash per-thread S/T and A partials ----
    float* rc = &redc[(wg * 32 + dq) * 8];
    #pragma unroll
    for (int j = 0; j < 4; ++j) { rc[j] = sS[j]; rc[4 + j] = sT[j]; }
    redA[t] = accA;
    __syncthreads();

    // ---- per-column reduce across the 8 token groups (t<128, d_local=t) ----
    float Sv = 0.f, Tv = 0.f;
    if (t < DH) {
        const int dq2 = t >> 2;
        const int j   = t & 3;
        #pragma unroll
        for (int w8 = 0; w8 < 8; ++w8) {
            const float* p = &redc[(w8 * 32 + dq2) * 8];
            Sv += p[j];
            Tv += p[4 + j];
        }
    }
    // ---- scalar A tree (all threads participate in syncs) ----
    for (int off = 128; off > 0; off >>= 1) {
        if (t < off) redA[t] += redA[t + off];
        __syncthreads();
    }

    // ---- global double accumulation ----
    if (t == 0) atomicAdd(&g_A, (double)redA[0]);
    if (t < DH) {
        const int d = doff + t;
        atomicAdd(&g_S[d],   (double)Sv);
        atomicAdd(&g_T[d],   (double)Tv);
        atomicAdd(&g_SX[d],  (double)csx);
        atomicAdd(&g_SX2[d], (double)csx2);
    }
    __threadfence();
    __syncthreads();      // all block atomics fenced before ticket
    if (t == 0) sLast = (atomicAdd(&g_count, 1u) == NBLK - 1) ? 1 : 0;
    __syncthreads();

    // ---- last block: double finalize + state re-zero for next replay ----
    if (sLast) {
        __threadfence();
        double* redD = (double*)xs;       // 256 doubles
        double c = 0.0;
        for (int d = t; d < DI; d += 256) {
            const double m1 = g_SX[d]  * (1.0 / NN);
            const double m2 = g_SX2[d] * (1.0 / NN);
            c += -m2 * g_S[d] + 2.0 * m1 * g_T[d];
        }
        redD[t] = c;
        __syncthreads();
        for (int off = 128; off > 0; off >>= 1) {
            if (t < off) redD[t] += redD[t + off];
            __syncthreads();
        }
        if (t == 0)
            out[0] = (float)((g_A + redD[0]) * (-0.5 / (double)NN));
        __syncthreads();
        for (int d = t; d < DI; d += 256) {
            g_S[d] = 0.0; g_T[d] = 0.0; g_SX[d] = 0.0; g_SX2[d] = 0.0;
        }
        if (t == 0) { g_A = 0.0; g_count = 0u; }
    }
}

extern "C" void kernel_launch(void* const* d_in, const int* in_sizes, int n_in,
                              void* d_out, int out_size) {
    const float* x  = (const float*)d_in[0];
    const float* mu = (const float*)d_in[1];
    const float* lv = (const float*)d_in[2];
    float* out = (float*)d_out;

    club_kernel<<<NBLK, 256>>>(x, mu, lv, out);
}